// round 12
// baseline (speedup 1.0000x reference)
#include <cuda_runtime.h>
#include <cuda_bf16.h>
#include <cstdint>
#include <cstddef>

// CompetitiveNetwork via mma.sync (m16n8k16 bf16, fp32 accum).
// R11: R9 body + __launch_bounds__(256, 2). R10's register hoist was a no-op
// (RF already pinned at 255 -> ptxas spilled the hoist; identical metrics).
// Real live state is ~110 regs, so capping at 128 regs doubles residency:
// 2 CTAs/SM = 16 warps/SM = 4 warps/SMSP on a latency-bound kernel where
// every pipe is <25% busy. Smem 2 x 82,944 B fits the 228 KB SM carveout.
// Everything else identical to R9: bt folded into matrices, +1 folded into
// accumulator init, 14 cheap (hi-only) + 4 precise (3-term split) iterations.

#define THREADS 256
#define ROWS_PER_CTA 128
#define N_DIM 64
#define CHEAP_ITERS 14

typedef unsigned int u32;

#define MATS_BYTES (6 * 8192)              // fragment-ordered split matrices
#define AT_OFF     MATS_BYTES
#define AT_STRIDE  66
#define SMEM_TOTAL (AT_OFF + 128 * AT_STRIDE * 4)   // 82944

__device__ __forceinline__ float rcpa(float x) {
    float r; asm("rcp.approx.f32 %0, %1;" : "=f"(r) : "f"(x)); return r;
}
__device__ __forceinline__ u32 packbf(float lo_elem, float hi_elem) {
    u32 r; asm("cvt.rn.bf16x2.f32 %0, %1, %2;" : "=r"(r)
               : "f"(hi_elem), "f"(lo_elem));
    return r;
}
__device__ __forceinline__ void split2(float x0, float x1, u32 &hi, u32 &lo) {
    hi = packbf(x0, x1);
    float h0 = __uint_as_float(hi << 16);
    float h1 = __uint_as_float(hi & 0xFFFF0000u);
    lo = packbf(x0 - h0, x1 - h1);
}

// fragment-order store: element at logical (k, n) of a B operand
__device__ __forceinline__ void st_frag(__nv_bfloat16* base, int k, int n,
                                        __nv_bfloat16 v) {
    int lane = ((n & 7) << 2) | ((k & 7) >> 1);
    int w2   = (((k >> 4) & 1) << 1) | ((k >> 3) & 1);
    int idx  = ((k >> 5) << 11) | ((n >> 3) << 8) | (lane << 3)
             | (w2 << 1) | (k & 1);
    base[idx] = v;
}

#define MMA(d, a, b0, b1)                                                      \
    asm("mma.sync.aligned.m16n8k16.row.col.f32.bf16.bf16.f32 "                 \
        "{%0,%1,%2,%3}, {%4,%5,%6,%7}, {%8,%9}, {%0,%1,%2,%3};"                \
        : "+f"((d)[0]), "+f"((d)[1]), "+f"((d)[2]), "+f"((d)[3])               \
        : "r"((a)[0]), "r"((a)[1]), "r"((a)[2]), "r"((a)[3]),                  \
          "r"(b0), "r"(b1))

// first MMA of an accumulator, C = 0 (epilogue H: no bias)
#define MMA_Z(d, a, b0, b1)                                                    \
    asm("mma.sync.aligned.m16n8k16.row.col.f32.bf16.bf16.f32 "                 \
        "{%0,%1,%2,%3}, {%4,%5,%6,%7}, {%8,%9}, {%10,%10,%10,%10};"            \
        : "=f"((d)[0]), "=f"((d)[1]), "=f"((d)[2]), "=f"((d)[3])               \
        : "r"((a)[0]), "r"((a)[1]), "r"((a)[2]), "r"((a)[3]),                  \
          "r"(b0), "r"(b1), "f"(0.0f))

// first MMA of an accumulator, C = 1 (folds the "+1.0" of the nonlinearity)
#define MMA_ONE(d, a, b0, b1)                                                  \
    asm("mma.sync.aligned.m16n8k16.row.col.f32.bf16.bf16.f32 "                 \
        "{%0,%1,%2,%3}, {%4,%5,%6,%7}, {%8,%9}, {%10,%10,%10,%10};"            \
        : "=f"((d)[0]), "=f"((d)[1]), "=f"((d)[2]), "=f"((d)[3])               \
        : "r"((a)[0]), "r"((a)[1]), "r"((a)[2]), "r"((a)[3]),                  \
          "r"(b0), "r"(b1), "f"(1.0f))

__global__ void __launch_bounds__(THREADS, 2)
cnet_mma_kernel(const float* __restrict__ AT,
                const float* __restrict__ Kraw,
                const float* __restrict__ BTraw,
                const float* __restrict__ Wraw,
                const float* __restrict__ braw,
                float* __restrict__ out)
{
    extern __shared__ char smc[];
    __nv_bfloat16* mats = reinterpret_cast<__nv_bfloat16*>(smc);
    float* ats = reinterpret_cast<float*>(smc + AT_OFF);   // [128][66] f32

    const int tid  = threadIdx.x;
    const int w    = tid >> 5;          // warp 0..7 -> rows [16w, 16w+16)
    const int lane = tid & 31;
    const int g    = lane >> 2;
    const int t    = lane & 3;
    const int rb   = w * 16;
    const int bid  = blockIdx.x;

    // ---- setup: exp/clip K, bt-folded fragment-ordered split matrices ------
    // mats 0/1: KT hi/lo   B(k=i,n=j) = K[i][j]           (BF-step)
    // mats 2/3: K'  hi/lo  B(k=j,n=i) = K[i][j]*bt[j]     (AF-step)
    // mats 4/5: M'  hi/lo  B(k=i,n=j) = K[i][j]*W*bt[j]   (epilogue)
    for (int idx = tid; idx < 4096; idx += THREADS) {
        int i = idx >> 6, j = idx & 63;
        float k = fminf(__expf(Kraw[idx]), 1000.0f);
        float btj = fminf(__expf(BTraw[j]), 1000.0f);
        float wv = fminf(fmaxf(Wraw[idx], -10.0f), 10.0f);
        float kp = k * btj;
        float m  = k * wv * btj;
        __nv_bfloat16 kh = __float2bfloat16_rn(k);
        __nv_bfloat16 kl = __float2bfloat16_rn(k - __bfloat162float(kh));
        __nv_bfloat16 ph = __float2bfloat16_rn(kp);
        __nv_bfloat16 pl = __float2bfloat16_rn(kp - __bfloat162float(ph));
        __nv_bfloat16 mh = __float2bfloat16_rn(m);
        __nv_bfloat16 ml = __float2bfloat16_rn(m - __bfloat162float(mh));
        st_frag(mats + 0 * 4096, i, j, kh);
        st_frag(mats + 1 * 4096, i, j, kl);
        st_frag(mats + 2 * 4096, j, i, ph);
        st_frag(mats + 3 * 4096, j, i, pl);
        st_frag(mats + 4 * 4096, i, j, mh);
        st_frag(mats + 5 * 4096, i, j, ml);
    }
    {
        const float4* atg = reinterpret_cast<const float4*>(
            AT + (size_t)bid * (ROWS_PER_CTA * N_DIM));
        for (int idx = tid; idx < 2048; idx += THREADS) {
            float4 v = atg[idx];
            int r = idx >> 4, c = (idx & 15) << 2;
            float* p = ats + r * AT_STRIDE + c;
            p[0] = v.x; p[1] = v.y; p[2] = v.z; p[3] = v.w;
        }
    }
    __syncthreads();

    const int rlo = (rb + g) * AT_STRIDE;
    const int rhi = (rb + 8 + g) * AT_STRIDE;

    // ---- fragment registers --------------------------------------------------
    float d[8][4];            // D frags: [nt][c]
    u32 ah[4][4], al[4][4];   // A frags hi/lo

    // initial A = bf16(AT) (hi only; lo joins at the precision boundary)
    #pragma unroll
    for (int kt = 0; kt < 4; kt++) {
        int cb = 16 * kt + 2 * t;
        float2 p0 = *reinterpret_cast<const float2*>(ats + rlo + cb);
        float2 p1 = *reinterpret_cast<const float2*>(ats + rhi + cb);
        float2 p2 = *reinterpret_cast<const float2*>(ats + rlo + cb + 8);
        float2 p3 = *reinterpret_cast<const float2*>(ats + rhi + cb + 8);
        ah[kt][0] = packbf(p0.x, p0.y);
        ah[kt][1] = packbf(p1.x, p1.y);
        ah[kt][2] = packbf(p2.x, p2.y);
        ah[kt][3] = packbf(p3.x, p3.y);
    }

    const uint4* __restrict__ frag = reinterpret_cast<const uint4*>(smc) + lane;

    // cheap matvec: d = A_hi @ B_hi + 1
#define MMA_PHASE_CHEAP(MH)                                                    \
    do {                                                                       \
        _Pragma("unroll")                                                      \
        for (int nt = 0; nt < 8; nt++) {                                       \
            uint4 h0 = frag[(MH) * 512 +       nt * 32];                       \
            uint4 h1 = frag[(MH) * 512 + 256 + nt * 32];                       \
            MMA_ONE(d[nt], ah[0], h0.x, h0.y);                                 \
            MMA(d[nt], ah[1], h0.z, h0.w);                                     \
            MMA(d[nt], ah[2], h1.x, h1.y);                                     \
            MMA(d[nt], ah[3], h1.z, h1.w);                                     \
        }                                                                      \
    } while (0)

    // full matvec: d = (Ah+Al) @ Bh + Ah @ Bl + BIAS (BIAS = MMA_ONE/MMA_Z)
#define MMA_PHASE_FULL(MH, FIRST)                                              \
    do {                                                                       \
        _Pragma("unroll")                                                      \
        for (int nt = 0; nt < 8; nt++) {                                       \
            uint4 h0 = frag[(MH) * 512 +       nt * 32];                       \
            uint4 h1 = frag[(MH) * 512 + 256 + nt * 32];                       \
            uint4 l0 = frag[((MH)+1) * 512 +       nt * 32];                   \
            uint4 l1 = frag[((MH)+1) * 512 + 256 + nt * 32];                   \
            FIRST(d[nt], ah[0], h0.x, h0.y);                                   \
            MMA(d[nt], al[0], h0.x, h0.y);                                     \
            MMA(d[nt], ah[0], l0.x, l0.y);                                     \
            MMA(d[nt], ah[1], h0.z, h0.w);                                     \
            MMA(d[nt], al[1], h0.z, h0.w);                                     \
            MMA(d[nt], ah[1], l0.z, l0.w);                                     \
            MMA(d[nt], ah[2], h1.x, h1.y);                                     \
            MMA(d[nt], al[2], h1.x, h1.y);                                     \
            MMA(d[nt], ah[2], l1.x, l1.y);                                     \
            MMA(d[nt], ah[3], h1.z, h1.w);                                     \
            MMA(d[nt], al[3], h1.z, h1.w);                                     \
            MMA(d[nt], ah[3], l1.z, l1.w);                                     \
        }                                                                      \
    } while (0)

    // BF' nonlinearity: d = rcp(d)   (bt folded into next matrix)
#define BF_NONLIN()                                                            \
    do {                                                                       \
        _Pragma("unroll")                                                      \
        for (int nt = 0; nt < 8; nt++) {                                       \
            d[nt][0] = rcpa(d[nt][0]);                                         \
            d[nt][1] = rcpa(d[nt][1]);                                         \
            d[nt][2] = rcpa(d[nt][2]);                                         \
            d[nt][3] = rcpa(d[nt][3]);                                         \
        }                                                                      \
    } while (0)

    // AF nonlinearity: d = AT * rcp(d)
#define AF_NONLIN()                                                            \
    do {                                                                       \
        _Pragma("unroll")                                                      \
        for (int nt = 0; nt < 8; nt++) {                                       \
            int cb = 8 * nt + 2 * t;                                           \
            float2 plo = *reinterpret_cast<const float2*>(ats + rlo + cb);     \
            float2 phi = *reinterpret_cast<const float2*>(ats + rhi + cb);     \
            d[nt][0] = plo.x * rcpa(d[nt][0]);                                 \
            d[nt][1] = plo.y * rcpa(d[nt][1]);                                 \
            d[nt][2] = phi.x * rcpa(d[nt][2]);                                 \
            d[nt][3] = phi.y * rcpa(d[nt][3]);                                 \
        }                                                                      \
    } while (0)

    // cheap repack: d -> ah only
#define REPACK_CHEAP()                                                         \
    do {                                                                       \
        _Pragma("unroll")                                                      \
        for (int kt = 0; kt < 4; kt++) {                                       \
            ah[kt][0] = packbf(d[2*kt][0],   d[2*kt][1]);                      \
            ah[kt][1] = packbf(d[2*kt][2],   d[2*kt][3]);                      \
            ah[kt][2] = packbf(d[2*kt+1][0], d[2*kt+1][1]);                    \
            ah[kt][3] = packbf(d[2*kt+1][2], d[2*kt+1][3]);                    \
        }                                                                      \
    } while (0)

    // full repack: d -> (ah, al)
#define REPACK_FULL()                                                          \
    do {                                                                       \
        _Pragma("unroll")                                                      \
        for (int kt = 0; kt < 4; kt++) {                                       \
            split2(d[2*kt][0],   d[2*kt][1],   ah[kt][0], al[kt][0]);          \
            split2(d[2*kt][2],   d[2*kt][3],   ah[kt][1], al[kt][1]);          \
            split2(d[2*kt+1][0], d[2*kt+1][1], ah[kt][2], al[kt][2]);          \
            split2(d[2*kt+1][2], d[2*kt+1][3], ah[kt][3], al[kt][3]);          \
        }                                                                      \
    } while (0)

    // ---- phase 1: 14 cheap iterations (hi-only) -----------------------------
    #pragma unroll 1
    for (int it = 0; it < CHEAP_ITERS; ++it) {
        MMA_PHASE_CHEAP(0);   // BF-step: d = KT^T(AF) + 1
        BF_NONLIN();          // BF' = rcp(d)
        REPACK_CHEAP();
        MMA_PHASE_CHEAP(2);   // AF-step: d = K'(BF') + 1
        AF_NONLIN();          // AF = AT * rcp(d)
        REPACK_CHEAP();
    }

    // precision boundary: lo residuals start at zero
    #pragma unroll
    for (int kt = 0; kt < 4; kt++)
        #pragma unroll
        for (int r = 0; r < 4; r++) al[kt][r] = 0u;

    // ---- phase 2: 3 precise BF/AF pairs, then final BF ----------------------
    #pragma unroll 1
    for (int it = 0; it < 3; ++it) {
        MMA_PHASE_FULL(0, MMA_ONE);
        BF_NONLIN();
        REPACK_FULL();
        MMA_PHASE_FULL(2, MMA_ONE);
        AF_NONLIN();
        REPACK_FULL();
    }

    // final BF step: keep fp32 BF' for the output contraction
    MMA_PHASE_FULL(0, MMA_ONE);
    BF_NONLIN();

    // stash final BF' (fp32) into the AT region (AT dead; same-lane rw)
    #pragma unroll
    for (int nt = 0; nt < 8; nt++) {
        int cb = 8 * nt + 2 * t;
        *reinterpret_cast<float2*>(ats + rlo + cb) =
            make_float2(d[nt][0], d[nt][1]);
        *reinterpret_cast<float2*>(ats + rhi + cb) =
            make_float2(d[nt][2], d[nt][3]);
    }

    // epilogue: H = AF @ M' (C = 0); y = sum_j BF'_j H_j
    MMA_PHASE_FULL(4, MMA_Z);

    float y0 = 0.f, y1 = 0.f;
    #pragma unroll
    for (int nt = 0; nt < 8; nt++) {
        int cb = 8 * nt + 2 * t;
        float2 blo = *reinterpret_cast<const float2*>(ats + rlo + cb);
        float2 bhi = *reinterpret_cast<const float2*>(ats + rhi + cb);
        y0 = fmaf(blo.x, d[nt][0], fmaf(blo.y, d[nt][1], y0));
        y1 = fmaf(bhi.x, d[nt][2], fmaf(bhi.y, d[nt][3], y1));
    }

    y0 += __shfl_xor_sync(0xFFFFFFFFu, y0, 1);
    y0 += __shfl_xor_sync(0xFFFFFFFFu, y0, 2);
    y1 += __shfl_xor_sync(0xFFFFFFFFu, y1, 1);
    y1 += __shfl_xor_sync(0xFFFFFFFFu, y1, 2);

    if (t == 0) {
        float bc = fminf(fmaxf(braw[0], -10.0f), 10.0f);
        size_t base = (size_t)bid * ROWS_PER_CTA + rb + g;
        out[base + 0] = y0 + bc;
        out[base + 8] = y1 + bc;
    }
}

extern "C" void kernel_launch(void* const* d_in, const int* in_sizes, int n_in,
                              void* d_out, int out_size)
{
    const float* AT    = (const float*)d_in[0];
    const float* Kraw  = (const float*)d_in[1];
    const float* BTraw = (const float*)d_in[2];
    const float* Wraw  = (const float*)d_in[3];
    const float* braw  = (const float*)d_in[4];
    float* out = (float*)d_out;

    const int B = in_sizes[0] / N_DIM;          // 16384
    const int grid = B / ROWS_PER_CTA;          // 128

    cudaFuncSetAttribute(cnet_mma_kernel,
                         cudaFuncAttributeMaxDynamicSharedMemorySize,
                         SMEM_TOTAL);

    cnet_mma_kernel<<<grid, THREADS, SMEM_TOTAL>>>(
        AT, Kraw, BTraw, Wraw, braw, out);
}

// round 13
// speedup vs baseline: 1.5484x; 1.5484x over previous
#include <cuda_runtime.h>
#include <cuda_fp16.h>
#include <cstdint>
#include <cstddef>

// CompetitiveNetwork via mma.sync (m16n8k16 f16, fp32 accum).
// R12: revert R11 (grid=128 < 148 SMs -> no 2nd CTA existed; reg cap only
// added spills). Base = R9 body (proven 41.7us). Change: all operands
// bf16 -> fp16 (10-bit mantissa, same MMA shape/layout/throughput, base
// PTX). 4x lower cheap-phase noise buys one precise BF/AF pair -> schedule
// is 15 cheap + 2 precise pairs + final precise BF (18 BF / 17 AF total,
// same as before; MMA count -8%). Error model: cheap steady-state ~2^-11
// /(1-rho) contracted by rho^3 + fp16 3-term floor 2^-22 => ~1e-4.

#define THREADS 256
#define ROWS_PER_CTA 128
#define N_DIM 64
#define CHEAP_ITERS 15

typedef unsigned int u32;

#define MATS_BYTES (6 * 8192)              // fragment-ordered split matrices
#define AT_OFF     MATS_BYTES
#define AT_STRIDE  66
#define SMEM_TOTAL (AT_OFF + 128 * AT_STRIDE * 4)   // 82944

__device__ __forceinline__ float rcpa(float x) {
    float r; asm("rcp.approx.f32 %0, %1;" : "=f"(r) : "f"(x)); return r;
}
__device__ __forceinline__ u32 packh2(float x0, float x1) {
    __half2 h = __floats2half2_rn(x0, x1);
    return *reinterpret_cast<u32*>(&h);
}
__device__ __forceinline__ void split2h(float x0, float x1, u32 &hi, u32 &lo) {
    __half2 h = __floats2half2_rn(x0, x1);
    hi = *reinterpret_cast<u32*>(&h);
    float h0 = __low2float(h), h1 = __high2float(h);
    __half2 l = __floats2half2_rn(x0 - h0, x1 - h1);
    lo = *reinterpret_cast<u32*>(&l);
}

// fragment-order store: element at logical (k, n) of a B operand
__device__ __forceinline__ void st_frag(__half* base, int k, int n, __half v) {
    int lane = ((n & 7) << 2) | ((k & 7) >> 1);
    int w2   = (((k >> 4) & 1) << 1) | ((k >> 3) & 1);
    int idx  = ((k >> 5) << 11) | ((n >> 3) << 8) | (lane << 3)
             | (w2 << 1) | (k & 1);
    base[idx] = v;
}

#define MMA(d, a, b0, b1)                                                      \
    asm("mma.sync.aligned.m16n8k16.row.col.f32.f16.f16.f32 "                   \
        "{%0,%1,%2,%3}, {%4,%5,%6,%7}, {%8,%9}, {%0,%1,%2,%3};"                \
        : "+f"((d)[0]), "+f"((d)[1]), "+f"((d)[2]), "+f"((d)[3])               \
        : "r"((a)[0]), "r"((a)[1]), "r"((a)[2]), "r"((a)[3]),                  \
          "r"(b0), "r"(b1))

// first MMA of an accumulator, C = 0 (epilogue H: no bias)
#define MMA_Z(d, a, b0, b1)                                                    \
    asm("mma.sync.aligned.m16n8k16.row.col.f32.f16.f16.f32 "                   \
        "{%0,%1,%2,%3}, {%4,%5,%6,%7}, {%8,%9}, {%10,%10,%10,%10};"            \
        : "=f"((d)[0]), "=f"((d)[1]), "=f"((d)[2]), "=f"((d)[3])               \
        : "r"((a)[0]), "r"((a)[1]), "r"((a)[2]), "r"((a)[3]),                  \
          "r"(b0), "r"(b1), "f"(0.0f))

// first MMA of an accumulator, C = 1 (folds the "+1.0" of the nonlinearity)
#define MMA_ONE(d, a, b0, b1)                                                  \
    asm("mma.sync.aligned.m16n8k16.row.col.f32.f16.f16.f32 "                   \
        "{%0,%1,%2,%3}, {%4,%5,%6,%7}, {%8,%9}, {%10,%10,%10,%10};"            \
        : "=f"((d)[0]), "=f"((d)[1]), "=f"((d)[2]), "=f"((d)[3])               \
        : "r"((a)[0]), "r"((a)[1]), "r"((a)[2]), "r"((a)[3]),                  \
          "r"(b0), "r"(b1), "f"(1.0f))

__global__ void __launch_bounds__(THREADS, 1)
cnet_mma_kernel(const float* __restrict__ AT,
                const float* __restrict__ Kraw,
                const float* __restrict__ BTraw,
                const float* __restrict__ Wraw,
                const float* __restrict__ braw,
                float* __restrict__ out)
{
    extern __shared__ char smc[];
    __half* mats = reinterpret_cast<__half*>(smc);
    float* ats = reinterpret_cast<float*>(smc + AT_OFF);   // [128][66] f32

    const int tid  = threadIdx.x;
    const int w    = tid >> 5;          // warp 0..7 -> rows [16w, 16w+16)
    const int lane = tid & 31;
    const int g    = lane >> 2;
    const int t    = lane & 3;
    const int rb   = w * 16;
    const int bid  = blockIdx.x;

    // ---- setup: exp/clip K, bt-folded fragment-ordered split matrices ------
    // mats 0/1: KT hi/lo   B(k=i,n=j) = K[i][j]           (BF-step)
    // mats 2/3: K'  hi/lo  B(k=j,n=i) = K[i][j]*bt[j]     (AF-step)
    // mats 4/5: M'  hi/lo  B(k=i,n=j) = K[i][j]*W*bt[j]   (epilogue)
    for (int idx = tid; idx < 4096; idx += THREADS) {
        int i = idx >> 6, j = idx & 63;
        float k = fminf(__expf(Kraw[idx]), 1000.0f);
        float btj = fminf(__expf(BTraw[j]), 1000.0f);
        float wv = fminf(fmaxf(Wraw[idx], -10.0f), 10.0f);
        float kp = k * btj;
        float m  = k * wv * btj;
        __half kh = __float2half_rn(k);
        __half kl = __float2half_rn(k - __half2float(kh));
        __half ph = __float2half_rn(kp);
        __half pl = __float2half_rn(kp - __half2float(ph));
        __half mh = __float2half_rn(m);
        __half ml = __float2half_rn(m - __half2float(mh));
        st_frag(mats + 0 * 4096, i, j, kh);
        st_frag(mats + 1 * 4096, i, j, kl);
        st_frag(mats + 2 * 4096, j, i, ph);
        st_frag(mats + 3 * 4096, j, i, pl);
        st_frag(mats + 4 * 4096, i, j, mh);
        st_frag(mats + 5 * 4096, i, j, ml);
    }
    {
        const float4* atg = reinterpret_cast<const float4*>(
            AT + (size_t)bid * (ROWS_PER_CTA * N_DIM));
        for (int idx = tid; idx < 2048; idx += THREADS) {
            float4 v = atg[idx];
            int r = idx >> 4, c = (idx & 15) << 2;
            float* p = ats + r * AT_STRIDE + c;
            p[0] = v.x; p[1] = v.y; p[2] = v.z; p[3] = v.w;
        }
    }
    __syncthreads();

    const int rlo = (rb + g) * AT_STRIDE;
    const int rhi = (rb + 8 + g) * AT_STRIDE;

    // ---- fragment registers --------------------------------------------------
    float d[8][4];            // D frags: [nt][c]
    u32 ah[4][4], al[4][4];   // A frags hi/lo

    // initial A = fp16(AT) (hi only; lo joins at the precision boundary)
    #pragma unroll
    for (int kt = 0; kt < 4; kt++) {
        int cb = 16 * kt + 2 * t;
        float2 p0 = *reinterpret_cast<const float2*>(ats + rlo + cb);
        float2 p1 = *reinterpret_cast<const float2*>(ats + rhi + cb);
        float2 p2 = *reinterpret_cast<const float2*>(ats + rlo + cb + 8);
        float2 p3 = *reinterpret_cast<const float2*>(ats + rhi + cb + 8);
        ah[kt][0] = packh2(p0.x, p0.y);
        ah[kt][1] = packh2(p1.x, p1.y);
        ah[kt][2] = packh2(p2.x, p2.y);
        ah[kt][3] = packh2(p3.x, p3.y);
    }

    const uint4* __restrict__ frag = reinterpret_cast<const uint4*>(smc) + lane;

    // cheap matvec: d = A_hi @ B_hi + 1
#define MMA_PHASE_CHEAP(MH)                                                    \
    do {                                                                       \
        _Pragma("unroll")                                                      \
        for (int nt = 0; nt < 8; nt++) {                                       \
            uint4 h0 = frag[(MH) * 512 +       nt * 32];                       \
            uint4 h1 = frag[(MH) * 512 + 256 + nt * 32];                       \
            MMA_ONE(d[nt], ah[0], h0.x, h0.y);                                 \
            MMA(d[nt], ah[1], h0.z, h0.w);                                     \
            MMA(d[nt], ah[2], h1.x, h1.y);                                     \
            MMA(d[nt], ah[3], h1.z, h1.w);                                     \
        }                                                                      \
    } while (0)

    // full matvec: d = (Ah+Al) @ Bh + Ah @ Bl + BIAS (BIAS = MMA_ONE/MMA_Z)
#define MMA_PHASE_FULL(MH, FIRST)                                              \
    do {                                                                       \
        _Pragma("unroll")                                                      \
        for (int nt = 0; nt < 8; nt++) {                                       \
            uint4 h0 = frag[(MH) * 512 +       nt * 32];                       \
            uint4 h1 = frag[(MH) * 512 + 256 + nt * 32];                       \
            uint4 l0 = frag[((MH)+1) * 512 +       nt * 32];                   \
            uint4 l1 = frag[((MH)+1) * 512 + 256 + nt * 32];                   \
            FIRST(d[nt], ah[0], h0.x, h0.y);                                   \
            MMA(d[nt], al[0], h0.x, h0.y);                                     \
            MMA(d[nt], ah[0], l0.x, l0.y);                                     \
            MMA(d[nt], ah[1], h0.z, h0.w);                                     \
            MMA(d[nt], al[1], h0.z, h0.w);                                     \
            MMA(d[nt], ah[1], l0.z, l0.w);                                     \
            MMA(d[nt], ah[2], h1.x, h1.y);                                     \
            MMA(d[nt], al[2], h1.x, h1.y);                                     \
            MMA(d[nt], ah[2], l1.x, l1.y);                                     \
            MMA(d[nt], ah[3], h1.z, h1.w);                                     \
            MMA(d[nt], al[3], h1.z, h1.w);                                     \
            MMA(d[nt], ah[3], l1.z, l1.w);                                     \
        }                                                                      \
    } while (0)

    // BF' nonlinearity: d = rcp(d)   (bt folded into next matrix)
#define BF_NONLIN()                                                            \
    do {                                                                       \
        _Pragma("unroll")                                                      \
        for (int nt = 0; nt < 8; nt++) {                                       \
            d[nt][0] = rcpa(d[nt][0]);                                         \
            d[nt][1] = rcpa(d[nt][1]);                                         \
            d[nt][2] = rcpa(d[nt][2]);                                         \
            d[nt][3] = rcpa(d[nt][3]);                                         \
        }                                                                      \
    } while (0)

    // AF nonlinearity: d = AT * rcp(d)
#define AF_NONLIN()                                                            \
    do {                                                                       \
        _Pragma("unroll")                                                      \
        for (int nt = 0; nt < 8; nt++) {                                       \
            int cb = 8 * nt + 2 * t;                                           \
            float2 plo = *reinterpret_cast<const float2*>(ats + rlo + cb);     \
            float2 phi = *reinterpret_cast<const float2*>(ats + rhi + cb);     \
            d[nt][0] = plo.x * rcpa(d[nt][0]);                                 \
            d[nt][1] = plo.y * rcpa(d[nt][1]);                                 \
            d[nt][2] = phi.x * rcpa(d[nt][2]);                                 \
            d[nt][3] = phi.y * rcpa(d[nt][3]);                                 \
        }                                                                      \
    } while (0)

    // cheap repack: d -> ah only
#define REPACK_CHEAP()                                                         \
    do {                                                                       \
        _Pragma("unroll")                                                      \
        for (int kt = 0; kt < 4; kt++) {                                       \
            ah[kt][0] = packh2(d[2*kt][0],   d[2*kt][1]);                      \
            ah[kt][1] = packh2(d[2*kt][2],   d[2*kt][3]);                      \
            ah[kt][2] = packh2(d[2*kt+1][0], d[2*kt+1][1]);                    \
            ah[kt][3] = packh2(d[2*kt+1][2], d[2*kt+1][3]);                    \
        }                                                                      \
    } while (0)

    // full repack: d -> (ah, al)
#define REPACK_FULL()                                                          \
    do {                                                                       \
        _Pragma("unroll")                                                      \
        for (int kt = 0; kt < 4; kt++) {                                       \
            split2h(d[2*kt][0],   d[2*kt][1],   ah[kt][0], al[kt][0]);         \
            split2h(d[2*kt][2],   d[2*kt][3],   ah[kt][1], al[kt][1]);         \
            split2h(d[2*kt+1][0], d[2*kt+1][1], ah[kt][2], al[kt][2]);         \
            split2h(d[2*kt+1][2], d[2*kt+1][3], ah[kt][3], al[kt][3]);         \
        }                                                                      \
    } while (0)

    // ---- phase 1: 15 cheap iterations (hi-only, fp16) -----------------------
    #pragma unroll 1
    for (int it = 0; it < CHEAP_ITERS; ++it) {
        MMA_PHASE_CHEAP(0);   // BF-step: d = KT^T(AF) + 1
        BF_NONLIN();          // BF' = rcp(d)
        REPACK_CHEAP();
        MMA_PHASE_CHEAP(2);   // AF-step: d = K'(BF') + 1
        AF_NONLIN();          // AF = AT * rcp(d)
        REPACK_CHEAP();
    }

    // precision boundary: lo residuals start at zero
    #pragma unroll
    for (int kt = 0; kt < 4; kt++)
        #pragma unroll
        for (int r = 0; r < 4; r++) al[kt][r] = 0u;

    // ---- phase 2: 2 precise BF/AF pairs, then final BF ----------------------
    #pragma unroll 1
    for (int it = 0; it < 2; ++it) {
        MMA_PHASE_FULL(0, MMA_ONE);
        BF_NONLIN();
        REPACK_FULL();
        MMA_PHASE_FULL(2, MMA_ONE);
        AF_NONLIN();
        REPACK_FULL();
    }

    // final BF step: keep fp32 BF' for the output contraction
    MMA_PHASE_FULL(0, MMA_ONE);
    BF_NONLIN();

    // stash final BF' (fp32) into the AT region (AT dead; same-lane rw)
    #pragma unroll
    for (int nt = 0; nt < 8; nt++) {
        int cb = 8 * nt + 2 * t;
        *reinterpret_cast<float2*>(ats + rlo + cb) =
            make_float2(d[nt][0], d[nt][1]);
        *reinterpret_cast<float2*>(ats + rhi + cb) =
            make_float2(d[nt][2], d[nt][3]);
    }

    // epilogue: H = AF @ M' (C = 0); y = sum_j BF'_j H_j
    MMA_PHASE_FULL(4, MMA_Z);

    float y0 = 0.f, y1 = 0.f;
    #pragma unroll
    for (int nt = 0; nt < 8; nt++) {
        int cb = 8 * nt + 2 * t;
        float2 blo = *reinterpret_cast<const float2*>(ats + rlo + cb);
        float2 bhi = *reinterpret_cast<const float2*>(ats + rhi + cb);
        y0 = fmaf(blo.x, d[nt][0], fmaf(blo.y, d[nt][1], y0));
        y1 = fmaf(bhi.x, d[nt][2], fmaf(bhi.y, d[nt][3], y1));
    }

    y0 += __shfl_xor_sync(0xFFFFFFFFu, y0, 1);
    y0 += __shfl_xor_sync(0xFFFFFFFFu, y0, 2);
    y1 += __shfl_xor_sync(0xFFFFFFFFu, y1, 1);
    y1 += __shfl_xor_sync(0xFFFFFFFFu, y1, 2);

    if (t == 0) {
        float bc = fminf(fmaxf(braw[0], -10.0f), 10.0f);
        size_t base = (size_t)bid * ROWS_PER_CTA + rb + g;
        out[base + 0] = y0 + bc;
        out[base + 8] = y1 + bc;
    }
}

extern "C" void kernel_launch(void* const* d_in, const int* in_sizes, int n_in,
                              void* d_out, int out_size)
{
    const float* AT    = (const float*)d_in[0];
    const float* Kraw  = (const float*)d_in[1];
    const float* BTraw = (const float*)d_in[2];
    const float* Wraw  = (const float*)d_in[3];
    const float* braw  = (const float*)d_in[4];
    float* out = (float*)d_out;

    const int B = in_sizes[0] / N_DIM;          // 16384
    const int grid = B / ROWS_PER_CTA;          // 128

    cudaFuncSetAttribute(cnet_mma_kernel,
                         cudaFuncAttributeMaxDynamicSharedMemorySize,
                         SMEM_TOTAL);

    cnet_mma_kernel<<<grid, THREADS, SMEM_TOTAL>>>(
        AT, Kraw, BTraw, Wraw, braw, out);
}